// round 16
// baseline (speedup 1.0000x reference)
#include <cuda_runtime.h>
#include <cuda_fp16.h>
#include <mma.h>
#include <stdint.h>

using namespace nvcuda;

#define NN 100000
#define NE 1600000
#define DH 128
#define NT256 391    // ceil(NN/256)

// ---- scratch (device globals; no allocation allowed) ----
__device__ int   g_deg[NN];
__device__ int   g_rowptr[NN + 1];
__device__ int   g_cursor[NN];
__device__ uint2 g_csr[NE];
__device__ __half g_agg[NN * DH];
__device__ __half g_x16[NN * DH];
__device__ __half g_h1[NN * DH];
__device__ __half g_h2[NN * DH];
__device__ __half g_w16[3 * 256 * 128];   // [layer][k][n] fp16

// ============ small helpers ============
__device__ __forceinline__ uint32_t hpack(__half a, __half b) {
    return (uint32_t)__half_as_ushort(a) | ((uint32_t)__half_as_ushort(b) << 16);
}
__device__ __forceinline__ void split_h(float v, __half& h, __half& l) {
    h = __float2half_rn(v);
    l = __float2half_rn(v - __half2float(h));
}
__device__ __forceinline__ float2 h2f2(uint32_t u) {
    __half2 b = *reinterpret_cast<__half2*>(&u);
    return __half22float2(b);
}

// ============ fused prep: zero deg + convert x + convert weights ============
#define XQUADS (NN * DH / 4)
#define WELEMS (3 * 256 * 128)
__global__ void prep_all_kernel(const float* __restrict__ x,
                                const float* __restrict__ Wrel1, const float* __restrict__ Wroot1,
                                const float* __restrict__ Wrel2, const float* __restrict__ Wroot2,
                                const float* __restrict__ Wrel3, const float* __restrict__ Wroot3,
                                __half* __restrict__ x16, __half* __restrict__ w16,
                                int* __restrict__ deg) {
    int i = blockIdx.x * blockDim.x + threadIdx.x;
    if (i < XQUADS) {
        float4 v = *reinterpret_cast<const float4*>(x + (size_t)i * 4);
        uint2 p = make_uint2(hpack(__float2half_rn(v.x), __float2half_rn(v.y)),
                             hpack(__float2half_rn(v.z), __float2half_rn(v.w)));
        *reinterpret_cast<uint2*>(x16 + (size_t)i * 4) = p;
    } else if (i < XQUADS + NN) {
        deg[i - XQUADS] = 0;
    } else if (i < XQUADS + NN + WELEMS) {
        int w = i - (XQUADS + NN);
        int l = w >> 15;
        int j = w & 32767;
        int k = j >> 7, n = j & 127;
        const float* Wrel  = (l == 0) ? Wrel1  : (l == 1) ? Wrel2  : Wrel3;
        const float* Wroot = (l == 0) ? Wroot1 : (l == 1) ? Wroot2 : Wroot3;
        float v = (k < 128) ? Wrel[k * 128 + n] : Wroot[(k - 128) * 128 + n];
        w16[w] = __float2half_rn(v);
    }
}

// ============ CSR build ============
__global__ void deg_count_kernel(const int* __restrict__ dst, int* __restrict__ deg) {
    int i = blockIdx.x * blockDim.x + threadIdx.x;
    if (i < NE) atomicAdd(&deg[dst[i]], 1);
}

__global__ void scan_kernel(const int* __restrict__ deg,
                            int* __restrict__ rowptr, int* __restrict__ cursor) {
    __shared__ int wsum[32];
    __shared__ int carry;
    const int tid = threadIdx.x, lane = tid & 31, warp = tid >> 5;
    if (tid == 0) carry = 0;
    __syncthreads();
    for (int base = 0; base < NN; base += 1024) {
        int i = base + tid;
        int v = (i < NN) ? deg[i] : 0;
        int s = v;
        #pragma unroll
        for (int off = 1; off < 32; off <<= 1) {
            int t = __shfl_up_sync(0xFFFFFFFF, s, off);
            if (lane >= off) s += t;
        }
        if (lane == 31) wsum[warp] = s;
        __syncthreads();
        if (warp == 0) {
            int w = wsum[lane];
            #pragma unroll
            for (int off = 1; off < 32; off <<= 1) {
                int t = __shfl_up_sync(0xFFFFFFFF, w, off);
                if (lane >= off) w += t;
            }
            wsum[lane] = w;
        }
        __syncthreads();
        int excl = s - v + (warp > 0 ? wsum[warp - 1] : 0) + carry;
        if (i < NN) { rowptr[i] = excl; cursor[i] = excl; }
        __syncthreads();
        if (tid == 0) carry += wsum[31];
        __syncthreads();
    }
    if (threadIdx.x == 0) rowptr[NN] = carry;
}

__global__ void fill_csr_kernel(const int* __restrict__ src, const int* __restrict__ dst,
                                const float* __restrict__ w, int* __restrict__ cursor,
                                uint2* __restrict__ csr) {
    int e = blockIdx.x * blockDim.x + threadIdx.x;
    if (e < NE) {
        int d = dst[e];
        int p = atomicAdd(&cursor[d], 1);
        csr[p] = make_uint2((unsigned)src[e], __float_as_uint(w[e]));
    }
}

// ============ aggregation: one warp per node; single fp16 plane ============
__global__ void gather_agg_kernel(const __half* __restrict__ in16,
                                  const int* __restrict__ rowptr,
                                  const uint2* __restrict__ csr,
                                  __half* __restrict__ agg) {
    unsigned gt = blockIdx.x * blockDim.x + threadIdx.x;
    unsigned node = gt >> 5;
    int lane = threadIdx.x & 31;
    if (node >= NN) return;
    int s0 = __ldg(rowptr + node);
    int s1 = __ldg(rowptr + node + 1);
    float4 acc = make_float4(0.f, 0.f, 0.f, 0.f);
    int e = s0;
    for (; e + 3 < s1; e += 4) {
        uint2 e_[4];
        #pragma unroll
        for (int q = 0; q < 4; q++) e_[q] = __ldg(csr + e + q);
        uint2 v_[4];
        #pragma unroll
        for (int q = 0; q < 4; q++)
            v_[q] = *reinterpret_cast<const uint2*>(in16 + (size_t)e_[q].x * DH + lane * 4);
        #pragma unroll
        for (int q = 0; q < 4; q++) {
            float w0 = __uint_as_float(e_[q].y);
            float2 a = h2f2(v_[q].x), b = h2f2(v_[q].y);
            acc.x = fmaf(w0, a.x, acc.x); acc.y = fmaf(w0, a.y, acc.y);
            acc.z = fmaf(w0, b.x, acc.z); acc.w = fmaf(w0, b.y, acc.w);
        }
    }
    for (; e < s1; e++) {
        uint2 e0 = __ldg(csr + e);
        uint2 v0 = *reinterpret_cast<const uint2*>(in16 + (size_t)e0.x * DH + lane * 4);
        float w0 = __uint_as_float(e0.y);
        float2 a = h2f2(v0.x), b = h2f2(v0.y);
        acc.x = fmaf(w0, a.x, acc.x); acc.y = fmaf(w0, a.y, acc.y);
        acc.z = fmaf(w0, b.x, acc.z); acc.w = fmaf(w0, b.y, acc.w);
    }
    float di = (s1 > s0) ? 1.0f / (float)(s1 - s0) : 0.f;
    acc.x *= di; acc.y *= di; acc.z *= di; acc.w *= di;

    uint2 p = make_uint2(hpack(__float2half_rn(acc.x), __float2half_rn(acc.y)),
                         hpack(__float2half_rn(acc.z), __float2half_rn(acc.w)));
    *reinterpret_cast<uint2*>(agg + (size_t)node * DH + lane * 4) = p;
}

// ============ persistent wmma GEMM: 256x128 tiles, single-product fp16 ============
// 8 warps (256 thr) as 4(row)x2(col); warp tile 64x64, acc[4][4] (128 regs).
// B fp16 plane resident. A: 8 chunks of 256x32, 3-stage cp.async ring, 1 barrier/chunk.
// Loader: one row per thread, FOUR 16B cp.asyncs = full 64B row.
#define BSTR 136
#define ASTR 24                              // bias A chunk stride
#define ASTR2 40                             // A ring stride (32 halves + 8 pad)
#define OFF_BH 0u                            // 256 x BSTR x 2 = 69632
#define OFF_BB 69632u                        // bias B: 16 x BSTR x 2 = 4352
#define OFF_AB 73984u                        // bias A: 16 x ASTR x 2 = 768
#define OFF_A  74752u                        // 3 stages x 20480
#define ASTAGE 20480u
#define GEMM_SMEM (74752 + 3 * 20480)        // 136192

__global__ void __launch_bounds__(256, 1) gemm_persist_kernel(
    const __half* __restrict__ agg, const __half* __restrict__ xin,
    const __half* __restrict__ w16,
    const float* __restrict__ bias,
    __half* __restrict__ outh, float* __restrict__ foutv, int final_layer)
{
    extern __shared__ char smem[];
    __half* BH = reinterpret_cast<__half*>(smem + OFF_BH);
    __half* BB = reinterpret_cast<__half*>(smem + OFF_BB);
    __half* AB = reinterpret_cast<__half*>(smem + OFF_AB);
    uint32_t smemA;
    {
        uint32_t a;
        asm("{ .reg .u64 t; cvta.to.shared.u64 t, %1; cvt.u32.u64 %0, t; }" : "=r"(a) : "l"(smem + OFF_A));
        smemA = a;
    }

    const int tid = threadIdx.x;
    const int wid = tid >> 5;
    const int wm = wid >> 1;      // 0..3 -> rows 64*wm
    const int wn = wid & 1;       // 0..1 -> cols 64*wn

    // one-time staging: B plane + bias chunks (256 threads)
    #pragma unroll
    for (int j = 0; j < 16; j++) {
        int f = tid + j * 256;
        int rr = f >> 4, c8 = f & 15;
        uint4 vh = *reinterpret_cast<const uint4*>(w16 + (size_t)rr * 128 + c8 * 8);
        *reinterpret_cast<uint4*>(BH + rr * BSTR + c8 * 8) = vh;
    }
    for (int i = tid; i < (16 * BSTR + 16 * ASTR) / 2; i += 256)
        reinterpret_cast<uint32_t*>(BB)[i] = 0;   // BB then AB contiguous
    __syncthreads();
    if (tid < 128) {
        __half h, l;
        split_h(bias[tid], h, l);
        BB[0 * BSTR + tid] = h;
        BB[1 * BSTR + tid] = l;
        if (tid < 16) {
            AB[tid * ASTR + 0] = __float2half_rn(1.0f);
            AB[tid * ASTR + 1] = __float2half_rn(1.0f);
        }
    }
    __syncthreads();

    for (int tile = blockIdx.x; tile < NT256; tile += 148) {
        const int row0 = tile * 256;
        const int grow = row0 + tid;          // one row per thread, 4x16B = 64B
        const int sz = (grow < NN) ? 16 : 0;

        // chunk c in [0,8): k = c*32..c*32+31 ; c<4 agg, c>=4 xin
        auto issue = [&](int c) {
            const __half* p = (c < 4) ? agg : xin;
            const int k0 = (c & 3) * 32;
            const __half* s = p + (size_t)grow * DH + k0;
            uint32_t d = smemA + (uint32_t)(c % 3) * ASTAGE + (uint32_t)(tid * ASTR2) * 2u;
            asm volatile("cp.async.cg.shared.global [%0], [%1], 16, %2;" :: "r"(d),       "l"(s),      "r"(sz));
            asm volatile("cp.async.cg.shared.global [%0], [%1], 16, %2;" :: "r"(d + 16u), "l"(s + 8),  "r"(sz));
            asm volatile("cp.async.cg.shared.global [%0], [%1], 16, %2;" :: "r"(d + 32u), "l"(s + 16), "r"(sz));
            asm volatile("cp.async.cg.shared.global [%0], [%1], 16, %2;" :: "r"(d + 48u), "l"(s + 24), "r"(sz));
            asm volatile("cp.async.commit_group;");
        };

        wmma::fragment<wmma::accumulator, 16, 16, 16, float> acc[4][4];
        #pragma unroll
        for (int i = 0; i < 4; i++)
            #pragma unroll
            for (int j = 0; j < 4; j++) wmma::fill_fragment(acc[i][j], 0.f);

        // bias rank-1 chunk (fa identical for all row-frags)
        {
            wmma::fragment<wmma::matrix_a, 16, 16, 16, __half, wmma::row_major> fa;
            wmma::load_matrix_sync(fa, AB, ASTR);
            #pragma unroll
            for (int j = 0; j < 4; j++) {
                wmma::fragment<wmma::matrix_b, 16, 16, 16, __half, wmma::row_major> fb;
                wmma::load_matrix_sync(fb, BB + 64 * wn + 16 * j, BSTR);
                #pragma unroll
                for (int i = 0; i < 4; i++)
                    wmma::mma_sync(acc[i][j], fa, fb, acc[i][j]);
            }
        }

        issue(0);
        issue(1);

        // ONE barrier per chunk: wait -> barrier -> issue(c+2) -> compute(c).
        #pragma unroll 1
        for (int c = 0; c < 8; c++) {
            if (c < 7) asm volatile("cp.async.wait_group 1;");
            else       asm volatile("cp.async.wait_group 0;");
            __syncthreads();
            if (c < 6) issue(c + 2);

            const __half* Ac = reinterpret_cast<const __half*>(smem + OFF_A + (c % 3) * ASTAGE);
            #pragma unroll
            for (int kk = 0; kk < 2; kk++) {
                const int krow = c * 32 + kk * 16;
                wmma::fragment<wmma::matrix_b, 16, 16, 16, __half, wmma::row_major> fbh[4];
                #pragma unroll
                for (int j = 0; j < 4; j++)
                    wmma::load_matrix_sync(fbh[j], BH + krow * BSTR + 64 * wn + 16 * j, BSTR);
                #pragma unroll
                for (int i = 0; i < 4; i++) {
                    wmma::fragment<wmma::matrix_a, 16, 16, 16, __half, wmma::row_major> fah;
                    wmma::load_matrix_sync(fah, Ac + (64 * wm + 16 * i) * ASTR2 + kk * 16, ASTR2);
                    #pragma unroll
                    for (int j = 0; j < 4; j++)
                        wmma::mma_sync(acc[i][j], fah, fbh[j], acc[i][j]);
                }
            }
        }

        // relu
        #pragma unroll
        for (int i = 0; i < 4; i++)
            #pragma unroll
            for (int j = 0; j < 4; j++)
                #pragma unroll
                for (int e = 0; e < acc[i][j].num_elements; e++)
                    acc[i][j].x[e] = fmaxf(acc[i][j].x[e], 0.f);

        if (final_layer && row0 + 256 <= NN) {
            __syncthreads();
            #pragma unroll
            for (int i = 0; i < 4; i++)
                #pragma unroll
                for (int j = 0; j < 4; j++)
                    wmma::store_matrix_sync(foutv + (size_t)(row0 + 64 * wm + 16 * i) * DH + 64 * wn + 16 * j,
                                            acc[i][j], DH, wmma::mem_row_major);
            __syncthreads();
        } else {
            // smem roundtrip in 4 phases of 64 rows (phase hh served by warps with wm==hh)
            float* scr = reinterpret_cast<float*>(smem + OFF_A);   // 64 x 132 f32 = 33792 <= 61440
            #pragma unroll 1
            for (int hh = 0; hh < 4; hh++) {
                __syncthreads();
                if (wm == hh) {
                    #pragma unroll
                    for (int i = 0; i < 4; i++)
                        #pragma unroll
                        for (int j = 0; j < 4; j++)
                            wmma::store_matrix_sync(scr + (16 * i) * 132 + 64 * wn + 16 * j,
                                                    acc[i][j], 132, wmma::mem_row_major);
                }
                __syncthreads();
                int r6 = tid >> 2;      // 0..63
                int part = tid & 3;     // 32 elems each
                int gr = row0 + hh * 64 + r6;
                if (gr < NN) {
                    const float* srow = scr + r6 * 132 + part * 32;
                    if (!final_layer) {
                        uint32_t hp[16];
                        #pragma unroll
                        for (int q = 0; q < 16; q++)
                            hp[q] = hpack(__float2half_rn(srow[2 * q]), __float2half_rn(srow[2 * q + 1]));
                        size_t off = (size_t)gr * DH + part * 32;
                        #pragma unroll
                        for (int q = 0; q < 4; q++)
                            *reinterpret_cast<uint4*>(outh + off + q * 8) =
                                *reinterpret_cast<uint4*>(hp + q * 4);
                    } else {
                        float* drow = foutv + (size_t)gr * DH + part * 32;
                        #pragma unroll
                        for (int q = 0; q < 8; q++)
                            *reinterpret_cast<float4*>(drow + q * 4) =
                                *reinterpret_cast<const float4*>(srow + q * 4);
                    }
                }
            }
            __syncthreads();   // scratch becomes A ring again next tile
        }
    }
}

// ============ host ============
extern "C" void kernel_launch(void* const* d_in, const int* in_sizes, int n_in,
                              void* d_out, int out_size) {
    const float* x      = (const float*)d_in[0];
    const int*   ei     = (const int*)d_in[1];
    const float* ea     = (const float*)d_in[2];
    const float* Wrel1  = (const float*)d_in[3];
    const float* b1     = (const float*)d_in[4];
    const float* Wroot1 = (const float*)d_in[5];
    const float* Wrel2  = (const float*)d_in[6];
    const float* b2     = (const float*)d_in[7];
    const float* Wroot2 = (const float*)d_in[8];
    const float* Wrel3  = (const float*)d_in[9];
    const float* b3     = (const float*)d_in[10];
    const float* Wroot3 = (const float*)d_in[11];
    float* out = (float*)d_out;

    const int* src = ei;
    const int* dst = ei + NE;

    int *deg, *rowptr, *cursor;
    uint2 *csr;
    __half *agg, *x16, *h1, *h2, *w16;
    cudaGetSymbolAddress((void**)&deg,    g_deg);
    cudaGetSymbolAddress((void**)&rowptr, g_rowptr);
    cudaGetSymbolAddress((void**)&cursor, g_cursor);
    cudaGetSymbolAddress((void**)&csr,    g_csr);
    cudaGetSymbolAddress((void**)&agg,    g_agg);
    cudaGetSymbolAddress((void**)&x16,    g_x16);
    cudaGetSymbolAddress((void**)&h1,     g_h1);
    cudaGetSymbolAddress((void**)&h2,     g_h2);
    cudaGetSymbolAddress((void**)&w16,    g_w16);

    cudaFuncSetAttribute(gemm_persist_kernel,
                         cudaFuncAttributeMaxDynamicSharedMemorySize, GEMM_SMEM);

    int prep_items = XQUADS + NN + WELEMS;
    prep_all_kernel<<<(prep_items + 255) / 256, 256>>>(
        x, Wrel1, Wroot1, Wrel2, Wroot2, Wrel3, Wroot3,
        x16, w16, deg);
    deg_count_kernel<<<(NE + 255) / 256, 256>>>(dst, deg);
    scan_kernel<<<1, 1024>>>(deg, rowptr, cursor);
    fill_csr_kernel<<<(NE + 255) / 256, 256>>>(src, dst, ea, cursor, csr);

    const __half* in16[3] = {x16, h1, h2};
    __half* oh[3] = {h1, h2, nullptr};
    const float* bv[3] = {b1, b2, b3};

    int gather_blocks = (NN * 32 + 255) / 256;
    for (int l = 0; l < 3; l++) {
        gather_agg_kernel<<<gather_blocks, 256>>>(in16[l], rowptr, csr, agg);
        gemm_persist_kernel<<<148, 256, GEMM_SMEM>>>(
            agg, in16[l], w16 + l * 32768, bv[l],
            oh[l], out, l == 2 ? 1 : 0);
    }
}